// round 11
// baseline (speedup 1.0000x reference)
#include <cuda_runtime.h>
#include <cuda_bf16.h>
#include <cuda_fp16.h>

// SAConv: B=4, C=G=COUT=64, D=1, H=W=56, K=7, PAD=3, RDIM=256.
//   q = x*wq; logit_t = (q+u)*wk*xw_t + (q+v)*ro_t,  ro_t = sum_c Wr[g,c]*r[g*4+c,t]
//   out = wv * sum_t softmax(logit)_t * xw_t   (no max-subtraction; |logit| small)
// Two horizontally adjacent pixels per thread; f32x2 packed logit/accum math;
// exponentials via packed fp16x2 MUFU (ex2.approx.f16x2) -> half the MUFU load.

#define KW    7
#define PADX  3
#define HH    56
#define WW    56
#define TH    8           // output rows per block tile -> grid = 7 x 256 = 1792
#define PW    62          // padded width 56+6
#define SROWS (TH + 6)    // 14 padded rows staged
#define NT    224         // 28 col-pairs x 8 rows; 2 adjacent pixels per thread
#define LOG2E 1.4426950408889634f

typedef unsigned long long u64;

__device__ __forceinline__ float rcpa(float x) {
    float y; asm("rcp.approx.ftz.f32 %0, %1;" : "=f"(y) : "f"(x)); return y;
}
__device__ __forceinline__ u64 pack2(float lo, float hi) {
    u64 r; asm("mov.b64 %0, {%1, %2};" : "=l"(r) : "f"(lo), "f"(hi)); return r;
}
__device__ __forceinline__ void unpack2(float& lo, float& hi, u64 v) {
    asm("mov.b64 {%0, %1}, %2;" : "=f"(lo), "=f"(hi) : "l"(v));
}
__device__ __forceinline__ u64 mul2(u64 a, u64 b) {
    u64 r; asm("mul.rn.f32x2 %0, %1, %2;" : "=l"(r) : "l"(a), "l"(b)); return r;
}
__device__ __forceinline__ u64 add2(u64 a, u64 b) {
    u64 r; asm("add.rn.f32x2 %0, %1, %2;" : "=l"(r) : "l"(a), "l"(b)); return r;
}
__device__ __forceinline__ u64 fma2(u64 a, u64 b, u64 c) {
    u64 r; asm("fma.rn.f32x2 %0, %1, %2, %3;" : "=l"(r) : "l"(a), "l"(b), "l"(c)); return r;
}
// Packed exp2 of two fp32 values via one fp16x2 MUFU op; returns packed f32x2.
__device__ __forceinline__ u64 exp2_2(float l0, float l1) {
    __half2 h = __floats2half2_rn(l0, l1);       // cvt.rn.f16x2.f32
    __half2 p = h2exp2(h);                        // ex2.approx.f16x2 (1 MUFU)
    float2 f = __half22float2(p);
    return pack2(f.x, f.y);
}

__global__ __launch_bounds__(NT, 5)
void saconv_kernel(const float* __restrict__ x,  const float* __restrict__ r,
                   const float* __restrict__ Wq, const float* __restrict__ Wk,
                   const float* __restrict__ Wv, const float* __restrict__ Wr,
                   const float* __restrict__ up, const float* __restrict__ vp,
                   float* __restrict__ out)
{
    __shared__ float sp[SROWS * PW];
    __shared__ float2 ro2[49];          // ro_t duplicated in both lanes

    const int tile  = blockIdx.x;        // 0..6 (row tiles)
    const int plane = blockIdx.y;        // 0..255 = b*64 + g
    const int g     = plane & 63;
    const int tid   = threadIdx.x;
    const int h0    = tile * TH;

    // Stage padded plane slice: padded rows [h0, h0+SROWS).
    const float* xp = x + (size_t)plane * HH * WW;
    #pragma unroll
    for (int k = 0; k < (SROWS * PW + NT - 1) / NT; k++) {
        int idx = tid + k * NT;
        if (idx < SROWS * PW) {
            int pr = idx / PW, pc = idx - pr * PW;
            int gh = h0 + pr - PADX;
            int gw = pc - PADX;
            float vv = 0.0f;
            if ((unsigned)gh < HH && (unsigned)gw < WW) vv = xp[gh * WW + gw];
            sp[idx] = vv;
        }
    }

    // ro[t] = sum_c Wr[g,0,c] * r[g*4+c, t], duplicated into both float2 lanes.
    if (tid < 49) {
        float s = 0.0f;
        #pragma unroll
        for (int c = 0; c < 4; c++)
            s = fmaf(Wr[g * 4 + c], r[(g * 4 + c) * 49 + tid], s);
        ro2[tid] = make_float2(s, s);
    }
    __syncthreads();

    const float wq = Wq[g], wk = Wk[g], wvw = Wv[g];
    const float u  = up[g], v  = vp[g];

    const int cp = tid % 28;             // column pair: cols 2cp, 2cp+1
    const int rg = tid / 28;             // output row within tile: 0..7
    const float* base = sp + rg * PW + 2 * cp;   // window origin (padded)
    float* outp = out + (size_t)plane * HH * WW + (size_t)(h0 + rg) * WW + 2 * cp;

    // Per-pixel affine coefficients (log2 domain).
    float q0 = base[3 * PW + 3] * wq;
    float q1 = base[3 * PW + 4] * wq;
    u64 a01 = pack2((q0 + u) * wk * LOG2E, (q1 + u) * wk * LOG2E);
    u64 b01 = pack2((q0 + v) * LOG2E,      (q1 + v) * LOG2E);

    u64 s01 = 0, A01 = 0;
    #pragma unroll
    for (int i = 0; i < KW; i++) {
        const float2* rp = (const float2*)(base + i * PW);
        float2 ra = rp[0], rb = rp[1], rc = rp[2], rd = rp[3];
        float fr[8] = {ra.x, ra.y, rb.x, rb.y, rc.x, rc.y, rd.x, rd.y};
        #pragma unroll
        for (int j = 0; j < KW; j++) {
            float2 rr = ro2[i * KW + j];
            u64 rod = pack2(rr.x, rr.y);
            u64 w01 = pack2(fr[j], fr[j + 1]);
            u64 l01 = fma2(a01, w01, mul2(b01, rod));
            float l0, l1; unpack2(l0, l1, l01);
            u64 p01 = exp2_2(l0, l1);
            s01 = add2(s01, p01);
            A01 = fma2(p01, w01, A01);
        }
    }

    float sa, sb, aa, ab;
    unpack2(sa, sb, s01);
    unpack2(aa, ab, A01);
    float2 o;
    o.x = aa * wvw * rcpa(sa);
    o.y = ab * wvw * rcpa(sb);
    *(float2*)outp = o;                  // STG.64 (8B-aligned: even column)
}

extern "C" void kernel_launch(void* const* d_in, const int* in_sizes, int n_in,
                              void* d_out, int out_size)
{
    const float* x  = (const float*)d_in[0];
    const float* r  = (const float*)d_in[1];
    const float* Wq = (const float*)d_in[2];
    const float* Wk = (const float*)d_in[3];
    const float* Wv = (const float*)d_in[4];
    const float* Wr = (const float*)d_in[5];
    const float* up = (const float*)d_in[6];
    const float* vp = (const float*)d_in[7];
    float* out = (float*)d_out;

    dim3 grid(HH / TH, 4 * 64);   // (7 row-tiles, 256 planes) = 1792 blocks
    saconv_kernel<<<grid, NT>>>(x, r, Wq, Wk, Wv, Wr, up, vp, out);
}

// round 14
// speedup vs baseline: 1.3844x; 1.3844x over previous
#include <cuda_runtime.h>
#include <cuda_bf16.h>

// SAConv: B=4, C=G=COUT=64, D=1, H=W=56, K=7, PAD=3, RDIM=256.
//   q = x*wq; logit_t = (q+u)*wk*xw_t + (q+v)*ro_t,  ro_t = sum_c Wr[g,c]*r[g*4+c,t]
//   out = wv * sum_t softmax(logit)_t * xw_t   (no max-subtraction; |logit| small)
// Two horizontally adjacent pixels per thread. u64-native f32x2 datapath:
// window rows loaded as LDS.64 pairs used directly by packed FMA; ro stored
// duplicated as u64 so its LDS.64 feeds mul2 with no packing MOVs.

#define KW    7
#define PADX  3
#define HH    56
#define WW    56
#define TH    8           // output rows per block tile -> grid = 7 x 256 = 1792
#define PW    62          // padded width 56+6
#define SROWS (TH + 6)    // 14 padded rows staged
#define NT    224         // 28 col-pairs x 8 rows; 2 adjacent pixels per thread
#define LOG2E 1.4426950408889634f

typedef unsigned long long u64;

__device__ __forceinline__ float ex2a(float x) {
    float y; asm("ex2.approx.ftz.f32 %0, %1;" : "=f"(y) : "f"(x)); return y;
}
__device__ __forceinline__ float rcpa(float x) {
    float y; asm("rcp.approx.ftz.f32 %0, %1;" : "=f"(y) : "f"(x)); return y;
}
__device__ __forceinline__ u64 pack2(float lo, float hi) {
    u64 r; asm("mov.b64 %0, {%1, %2};" : "=l"(r) : "f"(lo), "f"(hi)); return r;
}
__device__ __forceinline__ void unpack2(float& lo, float& hi, u64 v) {
    asm("mov.b64 {%0, %1}, %2;" : "=f"(lo), "=f"(hi) : "l"(v));
}
__device__ __forceinline__ float lo32(u64 v) { float a, b; unpack2(a, b, v); return a; }
__device__ __forceinline__ float hi32(u64 v) { float a, b; unpack2(a, b, v); return b; }
// {hi(a), lo(b)} — the odd-j window pair
__device__ __forceinline__ u64 combo(u64 a, u64 b) { return pack2(hi32(a), lo32(b)); }
__device__ __forceinline__ u64 mul2(u64 a, u64 b) {
    u64 r; asm("mul.rn.f32x2 %0, %1, %2;" : "=l"(r) : "l"(a), "l"(b)); return r;
}
__device__ __forceinline__ u64 add2(u64 a, u64 b) {
    u64 r; asm("add.rn.f32x2 %0, %1, %2;" : "=l"(r) : "l"(a), "l"(b)); return r;
}
__device__ __forceinline__ u64 fma2(u64 a, u64 b, u64 c) {
    u64 r; asm("fma.rn.f32x2 %0, %1, %2, %3;" : "=l"(r) : "l"(a), "l"(b), "l"(c)); return r;
}
// exp2 both lanes of a packed pair -> packed pair
__device__ __forceinline__ u64 exp2_pair(u64 l) {
    float a, b; unpack2(a, b, l);
    return pack2(ex2a(a), ex2a(b));
}

__global__ __launch_bounds__(NT, 6)
void saconv_kernel(const float* __restrict__ x,  const float* __restrict__ r,
                   const float* __restrict__ Wq, const float* __restrict__ Wk,
                   const float* __restrict__ Wv, const float* __restrict__ Wr,
                   const float* __restrict__ up, const float* __restrict__ vp,
                   float* __restrict__ out)
{
    __shared__ float sp[SROWS * PW];
    __shared__ u64  rod[49];            // ro_t duplicated in both 32-bit lanes

    const int tile  = blockIdx.x;        // 0..6 (row tiles)
    const int plane = blockIdx.y;        // 0..255 = b*64 + g
    const int g     = plane & 63;
    const int tid   = threadIdx.x;
    const int h0    = tile * TH;

    // Stage padded plane slice: padded rows [h0, h0+SROWS).
    const float* xp = x + (size_t)plane * HH * WW;
    #pragma unroll
    for (int k = 0; k < (SROWS * PW + NT - 1) / NT; k++) {
        int idx = tid + k * NT;
        if (idx < SROWS * PW) {
            int pr = idx / PW, pc = idx - pr * PW;
            int gh = h0 + pr - PADX;
            int gw = pc - PADX;
            float vv = 0.0f;
            if ((unsigned)gh < HH && (unsigned)gw < WW) vv = xp[gh * WW + gw];
            sp[idx] = vv;
        }
    }

    // ro[t] = sum_c Wr[g,0,c] * r[g*4+c, t], duplicated into both lanes.
    if (tid < 49) {
        float s = 0.0f;
        #pragma unroll
        for (int c = 0; c < 4; c++)
            s = fmaf(Wr[g * 4 + c], r[(g * 4 + c) * 49 + tid], s);
        rod[tid] = pack2(s, s);
    }
    __syncthreads();

    const float wq = Wq[g], wk = Wk[g], wvw = Wv[g];
    const float u  = up[g], v  = vp[g];

    const int cp = tid % 28;             // column pair: cols 2cp, 2cp+1
    const int rg = tid / 28;             // output row within tile: 0..7
    const float* base = sp + rg * PW + 2 * cp;   // window origin (padded), 8B-aligned
    float* outp = out + (size_t)plane * HH * WW + (size_t)(h0 + rg) * WW + 2 * cp;

    // Per-pixel affine coefficients (log2 domain).
    float q0 = base[3 * PW + 3] * wq;
    float q1 = base[3 * PW + 4] * wq;
    u64 a01 = pack2((q0 + u) * wk * LOG2E, (q1 + u) * wk * LOG2E);
    u64 b01 = pack2((q0 + v) * LOG2E,      (q1 + v) * LOG2E);

    u64 s01 = 0, A01 = 0;
    #pragma unroll
    for (int i = 0; i < KW; i++) {
        const u64* rp = (const u64*)(base + i * PW);
        u64 r0 = rp[0], r1 = rp[1], r2 = rp[2], r3 = rp[3];
        const u64* rot = rod + i * KW;

        // j = 0,2,4,6: aligned pairs; j = 1,3,5: hi/lo recombines.
        u64 w, l, p;
        #define TERM(J, WPAIR)                                   \
            w = (WPAIR);                                         \
            l = fma2(a01, w, mul2(b01, rot[J]));                 \
            p = exp2_pair(l);                                    \
            s01 = add2(s01, p);                                  \
            A01 = fma2(p, w, A01);
        TERM(0, r0)
        TERM(1, combo(r0, r1))
        TERM(2, r1)
        TERM(3, combo(r1, r2))
        TERM(4, r2)
        TERM(5, combo(r2, r3))
        TERM(6, r3)
        #undef TERM
    }

    float sa, sb, aa, ab;
    unpack2(sa, sb, s01);
    unpack2(aa, ab, A01);
    float2 o;
    o.x = aa * wvw * rcpa(sa);
    o.y = ab * wvw * rcpa(sb);
    *(float2*)outp = o;                  // STG.64 (8B-aligned: even column)
}

extern "C" void kernel_launch(void* const* d_in, const int* in_sizes, int n_in,
                              void* d_out, int out_size)
{
    const float* x  = (const float*)d_in[0];
    const float* r  = (const float*)d_in[1];
    const float* Wq = (const float*)d_in[2];
    const float* Wk = (const float*)d_in[3];
    const float* Wv = (const float*)d_in[4];
    const float* Wr = (const float*)d_in[5];
    const float* up = (const float*)d_in[6];
    const float* vp = (const float*)d_in[7];
    float* out = (float*)d_out;

    dim3 grid(HH / TH, 4 * 64);   // (7 row-tiles, 256 planes) = 1792 blocks
    saconv_kernel<<<grid, NT>>>(x, r, Wq, Wk, Wv, Wr, up, vp, out);
}